// round 6
// baseline (speedup 1.0000x reference)
#include <cuda_runtime.h>
#include <stdint.h>

// Problem shape (fixed by the dataset)
#define N_DST 8192
#define N_SRC 32768
#define HW    2048              // 64*32 floats per row
#define ROW4  (HW / 4)          // 512 float4 per row
#define TOTAL4 (N_DST * ROW4)   // 4,194,304 float4 outputs
#define GRID   (TOTAL4 / 256)   // 16384 blocks
#define NSCAT  (N_SRC / 256)    // 128 scatter-role blocks (wave-1 resident)
#define BUCKET_CAP 64           // Poisson(4): P(overflow) ~ 1e-60

// Scratch in __device__ globals (no allocation allowed anywhere).
// Zero-initialized at module load; the kernel restores all of it to zero
// before exit so every graph replay sees identical state.
__device__ int g_counts[N_DST];
__device__ int g_bucket[N_DST * BUCKET_CAP];   // 2 MB
__device__ int g_zbar;    // barrier among the 128 scatter blocks
__device__ int g_ready;   // scatter-completion count (== NSCAT when done)
__device__ int g_done;    // grid-completion counter for cleanup election

__global__ void __launch_bounds__(256) fused_kernel(
    const float4* __restrict__ x,
    const float4* __restrict__ t,
    const int*    __restrict__ idxw,   // index viewed as int32 words
    float4* __restrict__ out)
{
    const int tid  = threadIdx.x;
    const int gid  = blockIdx.x * 256 + tid;   // output float4 id

    // Issue the x load immediately — its DRAM latency hides under the
    // scatter phase / ready-wait below.
    float4 v = x[gid];

    // ---------------- scatter role: blocks 0..127 ----------------
    if (blockIdx.x < NSCAT) {
        // Phase A: zero this block's 64-int slice of g_counts.
        if (tid < 64) g_counts[blockIdx.x * 64 + tid] = 0;
        __threadfence();
        __syncthreads();
        if (tid == 0) atomicAdd(&g_zbar, 1);
        // Barrier among the 128 co-resident scatter blocks.
        if (tid == 0) {
            while (*(volatile int*)&g_zbar != NSCAT) __nanosleep(32);
        }
        __syncthreads();
        __threadfence();

        // Phase B: dtype-detect + scatter this block's 256 source ids.
        // View idx as int32 words; word gid is in-bounds for both
        // int32[32768] and int64[32768]. If ALL odd words in this block's
        // window are zero -> little-endian int64 (high halves of 0..8191);
        // P(128 random int32 indices all zero) = 8192^-128 ~ 0.
        __shared__ int s_any;
        if (tid == 0) s_any = 0;
        int w = idxw[gid];
        __syncthreads();
        bool odd_nz = (gid & 1) && (w != 0);
        unsigned m = __ballot_sync(0xffffffffu, odd_nz);
        if ((tid & 31) == 0 && m) atomicOr(&s_any, 1);
        __syncthreads();
        bool is64 = (s_any == 0);
        int d = is64 ? (int)((const long long*)idxw)[gid] : w;

        int pos = atomicAdd(&g_counts[d], 1);
        if (pos < BUCKET_CAP)
            g_bucket[d * BUCKET_CAP + pos] = gid;

        __threadfence();
        __syncthreads();
        if (tid == 0) atomicAdd(&g_ready, 1);
    }

    // ---------------- wait for scatter completion ----------------
    {
        __shared__ int s_go;
        if (tid == 0) {
            while (*(volatile int*)&g_ready != NSCAT) __nanosleep(64);
            __threadfence();
            s_go = 1;
        }
        __syncthreads();
        (void)s_go;
    }

    // ---------------- gather-max (streaming phase) ----------------
    const int d = gid >> 9;          // / ROW4
    const int c = gid & (ROW4 - 1);  // % ROW4

    int k = g_counts[d];
    if (k > BUCKET_CAP) k = BUCKET_CAP;
    const int* bucket = &g_bucket[d * BUCKET_CAP];

    int s = 0;
    for (; s + 4 <= k; s += 4) {
        int i0 = bucket[s + 0];
        int i1 = bucket[s + 1];
        int i2 = bucket[s + 2];
        int i3 = bucket[s + 3];
        float4 t0 = __ldcs(&t[i0 * ROW4 + c]);
        float4 t1 = __ldcs(&t[i1 * ROW4 + c]);
        float4 t2 = __ldcs(&t[i2 * ROW4 + c]);
        float4 t3 = __ldcs(&t[i3 * ROW4 + c]);
        v.x = fmaxf(fmaxf(fmaxf(v.x, t0.x), fmaxf(t1.x, t2.x)), t3.x);
        v.y = fmaxf(fmaxf(fmaxf(v.y, t0.y), fmaxf(t1.y, t2.y)), t3.y);
        v.z = fmaxf(fmaxf(fmaxf(v.z, t0.z), fmaxf(t1.z, t2.z)), t3.z);
        v.w = fmaxf(fmaxf(fmaxf(v.w, t0.w), fmaxf(t1.w, t2.w)), t3.w);
    }
    for (; s < k; s++) {
        int sid = bucket[s];
        float4 tv = __ldcs(&t[sid * ROW4 + c]);
        v.x = fmaxf(v.x, tv.x);
        v.y = fmaxf(v.y, tv.y);
        v.z = fmaxf(v.z, tv.z);
        v.w = fmaxf(v.w, tv.w);
    }

    __stcs(&out[gid], v);

    // ---------------- cleanup: restore zeroed state for next replay -------
    __threadfence();
    __shared__ int s_last;
    if (tid == 0) s_last = (atomicAdd(&g_done, 1) == GRID - 1) ? 1 : 0;
    __syncthreads();
    if (s_last) {
        int4 z = make_int4(0, 0, 0, 0);
        int4* c4 = (int4*)g_counts;          // 2048 int4
        for (int j = tid; j < N_DST / 4; j += 256) c4[j] = z;
        if (tid == 0) {
            g_zbar = 0;
            g_ready = 0;
            __threadfence();
            g_done = 0;
        }
    }
}

// ---------------------------------------------------------------------------
extern "C" void kernel_launch(void* const* d_in, const int* in_sizes, int n_in,
                              void* d_out, int out_size) {
    // Identify inputs by element count, not position.
    const float4* x = 0;
    const float4* t = 0;
    const void*   idx = 0;
    for (int i = 0; i < n_in; i++) {
        long long sz = in_sizes[i];
        if (sz == (long long)N_DST * HW)      x   = (const float4*)d_in[i];
        else if (sz == (long long)N_SRC * HW) t   = (const float4*)d_in[i];
        else if (sz == N_SRC)                 idx = d_in[i];
    }
    float4* out = (float4*)d_out;
    (void)out_size;

    fused_kernel<<<GRID, 256>>>(x, t, (const int*)idx, out);
}

// round 7
// speedup vs baseline: 1.3058x; 1.3058x over previous
#include <cuda_runtime.h>
#include <stdint.h>

// Problem shape (fixed by the dataset)
#define N_DST 8192
#define N_SRC 32768
#define HW    2048              // 64*32 floats per row
#define ROW4  (HW / 4)          // 512 float4 per row
#define TOTAL4 (N_DST * ROW4)   // 4,194,304 float4 outputs
#define NSCAT  (N_SRC / 256)    // 128 scatter blocks (all wave-1 resident)
#define BUCKET_CAP 64           // Poisson(4): P(overflow) ~ 1e-60

// Scratch in __device__ globals (no allocation allowed anywhere).
__device__ int g_counts[N_DST];
__device__ int g_bucket[N_DST * BUCKET_CAP];   // 2 MB
__device__ int g_zbar;                         // zeroing barrier (reset below)

// ---------------------------------------------------------------------------
// Pass 0: zero counts + bucket scatter, single small kernel (128 blocks,
// all co-resident on 148 SMs -> spin barrier is deadlock-free and cheap).
__global__ void __launch_bounds__(256) scatter_kernel(const int* __restrict__ idxw) {
    const int tid = threadIdx.x;
    const int i   = blockIdx.x * 256 + tid;    // source element id 0..32767

    // Phase A: zero this block's 64-int slice of g_counts.
    if (tid < 64) g_counts[blockIdx.x * 64 + tid] = 0;
    __threadfence();
    __syncthreads();
    if (tid == 0) {
        int arrived = atomicAdd(&g_zbar, 1) + 1;
        if (arrived == NSCAT) g_zbar = 0;                 // reset for next replay
        else while (*(volatile int*)&g_zbar != 0) __nanosleep(32);
    }
    __syncthreads();
    __threadfence();

    // Phase B: dtype detect + scatter. View idx as int32 words; word i is
    // in-bounds for both int32[32768] and int64[32768]. If ALL odd words in
    // this block's window are zero -> little-endian int64 (high halves of
    // 0..8191); P(128 random int32 indices all zero) = 8192^-128 ~ 0.
    __shared__ int s_any;
    if (tid == 0) s_any = 0;
    int w = idxw[i];
    __syncthreads();
    bool odd_nz = (i & 1) && (w != 0);
    unsigned m = __ballot_sync(0xffffffffu, odd_nz);
    if ((tid & 31) == 0 && m) atomicOr(&s_any, 1);
    __syncthreads();
    bool is64 = (s_any == 0);
    int d = is64 ? (int)((const long long*)idxw)[i] : w;

    int pos = atomicAdd(&g_counts[d], 1);
    if (pos < BUCKET_CAP)
        g_bucket[d * BUCKET_CAP + pos] = i;
}

// ---------------------------------------------------------------------------
// Pass 1: gather-max. One block per dest row; each thread owns 2 float4
// columns (c and c+256) -> coalescing preserved, 2x per-thread MLP, k is
// block-uniform, half the blocks of the 1-per-thread version.
__global__ void __launch_bounds__(256) gather_kernel(
    const float4* __restrict__ x,
    const float4* __restrict__ t,
    float4* __restrict__ out)
{
    const int d  = blockIdx.x;            // dest row
    const int c0 = threadIdx.x;           // first column
    const int c1 = threadIdx.x + 256;     // second column
    const long base = (long)d * ROW4;

    float4 va = x[base + c0];
    float4 vb = x[base + c1];

    int k = g_counts[d];
    if (k > BUCKET_CAP) k = BUCKET_CAP;
    const int* bucket = &g_bucket[d * BUCKET_CAP];

    int s = 0;
    for (; s + 2 <= k; s += 2) {
        int i0 = bucket[s + 0];
        int i1 = bucket[s + 1];
        const float4* r0 = &t[(long)i0 * ROW4];
        const float4* r1 = &t[(long)i1 * ROW4];
        float4 a0 = __ldcs(r0 + c0);
        float4 b0 = __ldcs(r0 + c1);
        float4 a1 = __ldcs(r1 + c0);
        float4 b1 = __ldcs(r1 + c1);
        va.x = fmaxf(va.x, fmaxf(a0.x, a1.x));
        va.y = fmaxf(va.y, fmaxf(a0.y, a1.y));
        va.z = fmaxf(va.z, fmaxf(a0.z, a1.z));
        va.w = fmaxf(va.w, fmaxf(a0.w, a1.w));
        vb.x = fmaxf(vb.x, fmaxf(b0.x, b1.x));
        vb.y = fmaxf(vb.y, fmaxf(b0.y, b1.y));
        vb.z = fmaxf(vb.z, fmaxf(b0.z, b1.z));
        vb.w = fmaxf(vb.w, fmaxf(b0.w, b1.w));
    }
    if (s < k) {
        int i0 = bucket[s];
        const float4* r0 = &t[(long)i0 * ROW4];
        float4 a0 = __ldcs(r0 + c0);
        float4 b0 = __ldcs(r0 + c1);
        va.x = fmaxf(va.x, a0.x);
        va.y = fmaxf(va.y, a0.y);
        va.z = fmaxf(va.z, a0.z);
        va.w = fmaxf(va.w, a0.w);
        vb.x = fmaxf(vb.x, b0.x);
        vb.y = fmaxf(vb.y, b0.y);
        vb.z = fmaxf(vb.z, b0.z);
        vb.w = fmaxf(vb.w, b0.w);
    }

    __stcs(&out[base + c0], va);
    __stcs(&out[base + c1], vb);
}

// ---------------------------------------------------------------------------
extern "C" void kernel_launch(void* const* d_in, const int* in_sizes, int n_in,
                              void* d_out, int out_size) {
    // Identify inputs by element count, not position.
    const float4* x = 0;
    const float4* t = 0;
    const void*   idx = 0;
    for (int i = 0; i < n_in; i++) {
        long long sz = in_sizes[i];
        if (sz == (long long)N_DST * HW)      x   = (const float4*)d_in[i];
        else if (sz == (long long)N_SRC * HW) t   = (const float4*)d_in[i];
        else if (sz == N_SRC)                 idx = d_in[i];
    }
    float4* out = (float4*)d_out;
    (void)out_size;

    scatter_kernel<<<NSCAT, 256>>>((const int*)idx);
    gather_kernel<<<N_DST, 256>>>(x, t, out);
}